// round 1
// baseline (speedup 1.0000x reference)
#include <cuda_runtime.h>
#include <math.h>

#define B 16384
#define D 2048
#define E 16
#define C 64

// Scratch (no allocations allowed): routing buckets + counts.
__device__ int g_counts[E];
__device__ int g_bucket[E * B];

__global__ void zero_counts_kernel() {
    if (threadIdx.x < E) g_counts[threadIdx.x] = 0;
}

// ---------------------------------------------------------------------------
// Kernel 1: coarse router GEMM [B,E] + bias + argmax + bucket scatter.
// Block handles 32 samples; thread (s, e) accumulates experts e and e+8.
// ---------------------------------------------------------------------------
#define K1_TM 32
#define K1_KC 64

__global__ __launch_bounds__(256) void coarse_kernel(
    const float* __restrict__ features,
    const float* __restrict__ cw,
    const float* __restrict__ cb,
    float* __restrict__ out_coarse,
    float* __restrict__ out_eid)
{
    __shared__ float fs[K1_TM][K1_KC + 4];
    __shared__ float ws[E][K1_KC + 4];
    __shared__ float cs[K1_TM][E + 1];

    int tid = threadIdx.x;
    int s0 = blockIdx.x * K1_TM;
    int s = tid >> 3;   // 0..31 sample within tile
    int e = tid & 7;    // experts e and e+8

    float acc0 = 0.f, acc1 = 0.f;

    for (int k0 = 0; k0 < D; k0 += K1_KC) {
        {
            int r  = tid >> 4;   // 0..15
            int c4 = tid & 15;   // 0..15 float4 column
            float4 v0 = *(const float4*)(features + (size_t)(s0 + r) * D + k0 + c4 * 4);
            *(float4*)&fs[r][c4 * 4] = v0;
            float4 v1 = *(const float4*)(features + (size_t)(s0 + r + 16) * D + k0 + c4 * 4);
            *(float4*)&fs[r + 16][c4 * 4] = v1;
            float4 w = *(const float4*)(cw + (size_t)r * D + k0 + c4 * 4);
            *(float4*)&ws[r][c4 * 4] = w;
        }
        __syncthreads();
        #pragma unroll
        for (int kk = 0; kk < K1_KC; kk++) {
            float f = fs[s][kk];
            acc0 = fmaf(f, ws[e][kk], acc0);
            acc1 = fmaf(f, ws[e + 8][kk], acc1);
        }
        __syncthreads();
    }

    acc0 += cb[e];
    acc1 += cb[e + 8];
    cs[s][e]     = acc0;
    cs[s][e + 8] = acc1;
    out_coarse[(size_t)(s0 + s) * E + e]     = acc0;
    out_coarse[(size_t)(s0 + s) * E + e + 8] = acc1;
    __syncthreads();

    if (tid < K1_TM) {
        // first-occurrence argmax (matches jnp.argmax tie-breaking)
        float m = cs[tid][0];
        int am = 0;
        #pragma unroll
        for (int j = 1; j < E; j++) {
            float v = cs[tid][j];
            if (v > m) { m = v; am = j; }
        }
        int gs = s0 + tid;
        out_eid[gs] = (float)am;
        int pos = atomicAdd(&g_counts[am], 1);
        g_bucket[am * B + pos] = gs;
    }
}

// ---------------------------------------------------------------------------
// Kernel 2: per-expert gathered GEMM [cnt_e, C] + bias + softmax + argmax.
// Grid: (E, ceil(B/64)). Tile: 64 samples x 64 classes, K-chunks of 32.
// Staged tiles are TRANSPOSED in smem so compute reads are float4
// conflict-free (wb: contiguous, fa: broadcast).
// ---------------------------------------------------------------------------
#define K2_TM 64
#define K2_TN 64
#define K2_TK 32

__global__ __launch_bounds__(256) void expert_kernel(
    const float* __restrict__ features,
    const float* __restrict__ ew,
    const float* __restrict__ eb,
    float* __restrict__ out_local,
    float* __restrict__ out_global)
{
    int e  = blockIdx.x;
    int cnt = g_counts[e];
    int m0 = blockIdx.y * K2_TM;
    if (m0 >= cnt) return;

    __shared__ float fs[K2_TK][K2_TM + 4];   // [k][sample]
    __shared__ float ws[K2_TK][K2_TN + 4];   // [k][class]
    __shared__ float ys[K2_TM][K2_TN + 1];   // logits tile for epilogue
    __shared__ int   ridx[K2_TM];

    int tid = threadIdx.x;
    if (tid < K2_TM) {
        int r = m0 + tid;
        ridx[tid] = (r < cnt) ? g_bucket[e * B + r] : -1;
    }
    __syncthreads();

    int ty = tid >> 4;   // 0..15 -> rows 4*ty..4*ty+3
    int tx = tid & 15;   // 0..15 -> cols 4*tx..4*tx+3
    const float* wbase = ew + (size_t)e * C * D;

    float acc[4][4];
    #pragma unroll
    for (int i = 0; i < 4; i++)
        #pragma unroll
        for (int j = 0; j < 4; j++)
            acc[i][j] = 0.f;

    int lr  = tid >> 3;  // 0..31 (row within half-tile)
    int lc4 = tid & 7;   // 0..7  (float4 column: 8*16B = 128B contiguous/row)

    for (int k0 = 0; k0 < D; k0 += K2_TK) {
        #pragma unroll
        for (int it = 0; it < 2; it++) {
            int r = lr + it * 32;
            int row = ridx[r];
            float4 v = make_float4(0.f, 0.f, 0.f, 0.f);
            if (row >= 0)
                v = *(const float4*)(features + (size_t)row * D + k0 + lc4 * 4);
            fs[lc4 * 4 + 0][r] = v.x;
            fs[lc4 * 4 + 1][r] = v.y;
            fs[lc4 * 4 + 2][r] = v.z;
            fs[lc4 * 4 + 3][r] = v.w;
            int c = lr + it * 32;
            float4 w = *(const float4*)(wbase + (size_t)c * D + k0 + lc4 * 4);
            ws[lc4 * 4 + 0][c] = w.x;
            ws[lc4 * 4 + 1][c] = w.y;
            ws[lc4 * 4 + 2][c] = w.z;
            ws[lc4 * 4 + 3][c] = w.w;
        }
        __syncthreads();

        #pragma unroll
        for (int kk = 0; kk < K2_TK; kk++) {
            float4 fa = *(const float4*)&fs[kk][ty * 4];
            float4 wb = *(const float4*)&ws[kk][tx * 4];
            float fv[4] = {fa.x, fa.y, fa.z, fa.w};
            float wv[4] = {wb.x, wb.y, wb.z, wb.w};
            #pragma unroll
            for (int i = 0; i < 4; i++)
                #pragma unroll
                for (int j = 0; j < 4; j++)
                    acc[i][j] = fmaf(fv[i], wv[j], acc[i][j]);
        }
        __syncthreads();
    }

    // stash logits (+bias) in smem for row-wise epilogue
    #pragma unroll
    for (int i = 0; i < 4; i++)
        #pragma unroll
        for (int j = 0; j < 4; j++)
            ys[ty * 4 + i][tx * 4 + j] = acc[i][j] + eb[e * C + tx * 4 + j];
    __syncthreads();

    if (tid < K2_TM) {
        int r = m0 + tid;
        if (r < cnt) {
            int row = ridx[tid];
            float m = ys[tid][0];
            int am = 0;
            #pragma unroll
            for (int c = 1; c < C; c++) {
                float v = ys[tid][c];
                if (v > m) { m = v; am = c; }
            }
            float sum = 0.f;
            #pragma unroll
            for (int c = 0; c < C; c++) {
                float v = expf(ys[tid][c] - m);
                ys[tid][c] = v;
                sum += v;
            }
            float inv = 1.0f / sum;
            float* dst = out_local + (size_t)row * C;
            #pragma unroll
            for (int c = 0; c < C; c++) dst[c] = ys[tid][c] * inv;
            out_global[row] = (float)(am + e * C);
        }
    }
}

// ---------------------------------------------------------------------------
// Output layout (reference tuple order, flattened+concatenated, fp32):
//   [0,              B*E)              coarse_output
//   [B*E,            B*E+B)            expert_id (as float)
//   [B*E+B,          B*E+B+B*C)        local_preds
//   [B*E+B+B*C,      B*E+2B+B*C)       global_preds
// ---------------------------------------------------------------------------
extern "C" void kernel_launch(void* const* d_in, const int* in_sizes, int n_in,
                              void* d_out, int out_size) {
    const float* features = (const float*)d_in[0];
    const float* cw       = (const float*)d_in[1];
    const float* cb       = (const float*)d_in[2];
    const float* ew       = (const float*)d_in[3];
    const float* eb       = (const float*)d_in[4];

    float* out        = (float*)d_out;
    float* out_coarse = out;
    float* out_eid    = out + (size_t)B * E;
    float* out_local  = out_eid + B;
    float* out_global = out_local + (size_t)B * C;

    zero_counts_kernel<<<1, 32>>>();
    coarse_kernel<<<B / K1_TM, 256>>>(features, cw, cb, out_coarse, out_eid);
    dim3 g2(E, (B + K2_TM - 1) / K2_TM);
    expert_kernel<<<g2, 256>>>(features, ew, eb, out_local, out_global);
}